// round 5
// baseline (speedup 1.0000x reference)
#include <cuda_runtime.h>
#include <cuda_bf16.h>

// SGConv: out = (D^-1/2 A D^-1/2)^2 * feat @ W + b
// N=100000 nodes, 64 features, E=1000000 edges.
//
// Memory-guard constraints (learned R1/R3): large __device__ global segments
// (35-61MB) trigger a fixed 128MiB driver arena at first launch inside the
// harness checkpoint window. Pre-main CUDA calls break harness handles (R2).
// => globals kept to ~5.6MB; the h1 intermediate lives in d_out; the h2
//    intermediate lives in SHARED MEMORY of a persistent fused kernel.
//
// Pipeline:
//  1. histogram dst -> deg ; norm = rsqrt(max(deg,1))
//  2. exclusive scan -> rowptr ; CSR fill (src only; weights on the fly)
//  3. k_hop1: warp-per-dst gather  feat -> d_out  (= h1, every row written)
//  4. k_fused (nblocks <= #SMs, 1 block/SM pinned by big smem => all blocks
//     co-resident => software grid barrier is safe):
//       phase1: gather own h2 rows (reading d_out anywhere) into smem
//       grid barrier
//       phase2: out rows = h2 @ W + b  -> write back to own d_out rows

#define MAXN 100000
#define MAXE 1000000
#define F 64
#define SCAN_BLK 1024
// max dynamic smem opt-in on sm_100a is ~227KB; keep headroom:
// rows_pb*65*4 + 64*64*4 <= 224*1024  =>  rows_pb <= 819. Cap at 800.
#define ROWS_PB_CAP 800

__device__ int   g_deg[MAXN];
__device__ int   g_cur[MAXN];
__device__ int   g_rowptr[MAXN + 1];
__device__ int   g_chunksum[128];
__device__ int   g_chunkoff[128];
__device__ float g_norm[MAXN];
__device__ int   g_csr_src[MAXE];
__device__ int   g_bar;

// ---------------------------------------------------------------- zero
__global__ void k_zero(int N) {
    int i = blockIdx.x * blockDim.x + threadIdx.x;
    if (i < N) { g_deg[i] = 0; g_cur[i] = 0; }
    if (i == 0) g_bar = 0;
}

// ---------------------------------------------------------------- histogram
__global__ void k_hist(const int* __restrict__ dst, int E) {
    int e = blockIdx.x * blockDim.x + threadIdx.x;
    if (e < E) atomicAdd(&g_deg[dst[e]], 1);
}

// ---------------------------------------------------------------- norm
__global__ void k_norm(int N) {
    int i = blockIdx.x * blockDim.x + threadIdx.x;
    if (i < N) {
        float d = (float)g_deg[i];
        g_norm[i] = rsqrtf(fmaxf(d, 1.0f));
    }
}

// ---------------------------------------------------------------- scan
__global__ void k_scan1(int N) {
    __shared__ int sh[SCAN_BLK];
    int t = threadIdx.x;
    int i = blockIdx.x * SCAN_BLK + t;
    int v = (i < N) ? g_deg[i] : 0;
    sh[t] = v;
    __syncthreads();
    #pragma unroll
    for (int off = 1; off < SCAN_BLK; off <<= 1) {
        int x = (t >= off) ? sh[t - off] : 0;
        __syncthreads();
        sh[t] += x;
        __syncthreads();
    }
    if (i < N) g_rowptr[i] = sh[t] - v;          // exclusive (partial)
    if (t == SCAN_BLK - 1) g_chunksum[blockIdx.x] = sh[t];
}

__global__ void k_scan2(int nblocks) {
    if (threadIdx.x == 0 && blockIdx.x == 0) {
        int run = 0;
        for (int b = 0; b < nblocks; b++) {
            g_chunkoff[b] = run;
            run += g_chunksum[b];
        }
    }
}

__global__ void k_scan3(int N, int E) {
    int i = blockIdx.x * blockDim.x + threadIdx.x;
    if (i < N) g_rowptr[i] += g_chunkoff[i / SCAN_BLK];
    if (i == 0) g_rowptr[N] = E;
}

// ---------------------------------------------------------------- CSR fill
__global__ void k_fill(const int* __restrict__ src, const int* __restrict__ dst, int E) {
    int e = blockIdx.x * blockDim.x + threadIdx.x;
    if (e < E) {
        int d = dst[e];
        int p = g_rowptr[d] + atomicAdd(&g_cur[d], 1);
        g_csr_src[p] = src[e];
    }
}

// ---------------------------------------------------------------- hop1
// one warp per dst node; lane owns float2 (cols 2*lane, 2*lane+1)
__global__ void k_hop1(const float* __restrict__ x, float* __restrict__ y, int N) {
    int warp = (blockIdx.x * blockDim.x + threadIdx.x) >> 5;
    int lane = threadIdx.x & 31;
    if (warp >= N) return;
    int beg = g_rowptr[warp];
    int end = g_rowptr[warp + 1];
    float nd = g_norm[warp];
    float2 acc = make_float2(0.f, 0.f);
    const float2* xr = (const float2*)x;
    for (int j = beg; j < end; j++) {
        int   s = __ldg(&g_csr_src[j]);
        float w = nd * __ldg(&g_norm[s]);
        float2 v = xr[s * 32 + lane];
        acc.x += w * v.x;
        acc.y += w * v.y;
    }
    ((float2*)y)[warp * 32 + lane] = acc;
}

// ---------------------------------------------------------------- fused hop2 + GEMM
// nblocks <= #SMs, huge dyn smem forces 1 block/SM -> all blocks resident ->
// software grid barrier cannot deadlock.
// smem layout: h2[rows_pb][65] (padded) then W[64][64].
// x and out ALIAS (both d_out) -- phases separated by the grid barrier.
__global__ void __launch_bounds__(512, 1)
k_fused(const float* x, float* out, const float* __restrict__ Wm,
        const float* __restrict__ bias, int N, int rows_pb, int nblocks) {
    extern __shared__ float sm[];
    float* h2 = sm;                       // rows_pb * 65
    float* Ws = sm + rows_pb * 65;        // 64*64

    int tid  = threadIdx.x;
    int wid  = tid >> 5;
    int lane = tid & 31;
    int row0 = blockIdx.x * rows_pb;

    for (int i = tid; i < F * F; i += blockDim.x) Ws[i] = Wm[i];

    // ---- phase 1: gather h2 rows into smem (reads x = d_out anywhere)
    const float2* xr = (const float2*)x;
    for (int lr = wid; lr < rows_pb; lr += (int)(blockDim.x >> 5)) {
        int r = row0 + lr;
        float2 acc = make_float2(0.f, 0.f);
        if (r < N) {
            int beg = g_rowptr[r];
            int end = g_rowptr[r + 1];
            float nd = g_norm[r];
            for (int j = beg; j < end; j++) {
                int   s = __ldg(&g_csr_src[j]);
                float w = nd * __ldg(&g_norm[s]);
                float2 v = xr[s * 32 + lane];
                acc.x += w * v.x;
                acc.y += w * v.y;
            }
        }
        h2[lr * 65 + 2 * lane]     = acc.x;
        h2[lr * 65 + 2 * lane + 1] = acc.y;
    }

    // ---- software grid barrier (all nblocks co-resident by construction)
    __syncthreads();
    __threadfence();
    if (tid == 0) {
        atomicAdd(&g_bar, 1);
        while (*(volatile int*)&g_bar < nblocks) __nanosleep(64);
    }
    __syncthreads();
    __threadfence();

    // ---- phase 2: out rows = h2 @ W + b, 128-row tiles, 4x4 per thread
    int tx = tid & 15;          // 16 col groups
    int ty = tid >> 4;          // 32 row groups (covers 128 rows per tile)
    int c0 = tx * 4;
    float4 bv = *(const float4*)&bias[c0];

    for (int t0 = 0; t0 < rows_pb; t0 += 128) {
        float acc[4][4];
        #pragma unroll
        for (int i = 0; i < 4; i++) {
            acc[i][0] = bv.x; acc[i][1] = bv.y; acc[i][2] = bv.z; acc[i][3] = bv.w;
        }
        int rbase = t0 + ty * 4;
        // clamp smem reads to allocated region; stores are guarded below
        int rr[4];
        #pragma unroll
        for (int i = 0; i < 4; i++) {
            int r = rbase + i;
            rr[i] = (r < rows_pb) ? r : (rows_pb - 1);
        }
        #pragma unroll
        for (int k = 0; k < F; k++) {
            float4 wv = *(const float4*)&Ws[k * F + c0];
            #pragma unroll
            for (int i = 0; i < 4; i++) {
                float yv = h2[rr[i] * 65 + k];
                acc[i][0] += yv * wv.x;
                acc[i][1] += yv * wv.y;
                acc[i][2] += yv * wv.z;
                acc[i][3] += yv * wv.w;
            }
        }
        #pragma unroll
        for (int i = 0; i < 4; i++) {
            int lr = rbase + i;
            int g  = row0 + lr;
            if (lr < rows_pb && g < N) {
                float4 v = make_float4(acc[i][0], acc[i][1], acc[i][2], acc[i][3]);
                *(float4*)(out + g * F + c0) = v;
            }
        }
    }
}

// ---------------------------------------------------------------- launch
extern "C" void kernel_launch(void* const* d_in, const int* in_sizes, int n_in,
                              void* d_out, int out_size) {
    const float* feat = (const float*)d_in[0];
    const int*   src  = (const int*)d_in[1];
    const int*   dst  = (const int*)d_in[2];
    const float* Wm   = (const float*)d_in[3];
    const float* bias = (const float*)d_in[4];
    float* out = (float*)d_out;

    int N = in_sizes[0] / F;   // 100000
    int E = in_sizes[1];       // 1000000

    int dev = 0;
    cudaGetDevice(&dev);
    int smcount = 0;
    cudaDeviceGetAttribute(&smcount, cudaDevAttrMultiProcessorCount, dev);
    if (smcount <= 0) smcount = 148;

    // rows per block, capped so dynamic smem fits sm_100a's 227KB opt-in.
    int rows_pb = (N + smcount - 1) / smcount;
    if (rows_pb > ROWS_PB_CAP) rows_pb = ROWS_PB_CAP;
    int nblocks = (N + rows_pb - 1) / rows_pb;        // <= smcount guaranteed
    if (nblocks > smcount) nblocks = smcount;          // paranoia (residency)
    rows_pb = (N + nblocks - 1) / nblocks;             // recompute consistent
    size_t smem = (size_t)(rows_pb * 65 + F * F) * sizeof(float);
    cudaFuncSetAttribute(k_fused, cudaFuncAttributeMaxDynamicSharedMemorySize,
                         (int)smem);

    int nb_n   = (N + 255) / 256;
    int nb_e   = (E + 255) / 256;
    int nb_sc  = (N + SCAN_BLK - 1) / SCAN_BLK;
    int nb_hop = (N * 32 + 255) / 256;

    k_zero<<<nb_n, 256>>>(N);
    k_hist<<<nb_e, 256>>>(dst, E);
    k_norm<<<nb_n, 256>>>(N);
    k_scan1<<<nb_sc, SCAN_BLK>>>(N);
    k_scan2<<<1, 32>>>(nb_sc);
    k_scan3<<<nb_n, 256>>>(N, E);
    k_fill<<<nb_e, 256>>>(src, dst, E);
    k_hop1<<<nb_hop, 256>>>(feat, out, N);
    k_fused<<<nblocks, 512, smem>>>(out, out, Wm, bias, N, rows_pb, nblocks);
}